// round 4
// baseline (speedup 1.0000x reference)
#include <cuda_runtime.h>
#include <math.h>

#define BB 16
#define MM 32
#define WW 256
#define NN 65536      // 256*256
#define CC 27
#define T1 256

// ---- scratch (unique writer per element -> no data races) ----
__device__ __align__(16) unsigned char g_sem8[BB * NN];
__device__ float g_entArr[BB * MM];   // per-(b,m) entropy
__device__ float g_blkI[BB * MM];     // per-block boundary intersection partial
__device__ float g_blkU[BB * MM];     // per-block boundary union partial
__device__ float g_blkD[BB * MM];     // per-block dbc partial
__device__ unsigned int g_count = 0;  // last-block-done counter (reset by last block)

// ---------------------------------------------------------------------------
// Pack kernel: sem int32 -> uint8 (1 MiB; stays L2-resident for 32x reuse).
// ---------------------------------------------------------------------------
__global__ __launch_bounds__(256) void pack_kernel(const int* __restrict__ sem) {
    int i = blockIdx.x * 256 + threadIdx.x;     // over BB*NN/4 uchar4
    int4 v = ((const int4*)sem)[i];
    uchar4 o;
    o.x = (unsigned char)v.x; o.y = (unsigned char)v.y;
    o.z = (unsigned char)v.z; o.w = (unsigned char)v.w;
    ((uchar4*)g_sem8)[i] = o;
}

// ---------------------------------------------------------------------------
// Fused kernel: 512 blocks (one per (b,m)), 256 threads.
//  Part 1: boundary/depth losses on a 2048-px slice (vectorized, in-register
//          neighbors).
//  Part 2: masked class histogram via per-thread private column-major smem
//          bins (bank = tid%32 -> conflict-free RMW) + in-block entropy.
//  Tail:   last finished block computes the 4 output scalars.
// ---------------------------------------------------------------------------
__global__ __launch_bounds__(T1) void fused_kernel(const int* __restrict__ sem,
                                                   const float* __restrict__ masks,
                                                   const float* __restrict__ depth,
                                                   float* __restrict__ out) {
    __shared__ float s_hist[CC * T1];          // 27,648 B
    __shared__ float s_red[T1 / 32][CC];
    __shared__ float rI[T1 / 32], rU[T1 / 32], rD[T1 / 32];
    __shared__ bool  s_isLast;

    const int block = blockIdx.x;              // b*32 + m
    const int b     = block >> 5;
    const int tid   = threadIdx.x;
    const int lane  = tid & 31;
    const int wid   = tid >> 5;

    float* my = s_hist + tid;                  // bin c at my[c*T1]
#pragma unroll
    for (int c = 0; c < CC; c++) my[c * T1] = 0.f;

    // batch-local bases
    const int4*   semv = (const int4*)sem + ((size_t)b << 14);
    const float4* m0v  = (const float4*)(masks + (size_t)b * MM * NN);  // m=0 plane
    const float4* dv   = (const float4*)depth + ((size_t)b << 14);
    const int*    semS = sem + ((size_t)b << 16);
    const float*  m0S  = masks + (size_t)b * MM * NN;
    const float*  dS   = depth + ((size_t)b << 16);

    // ---- Part 1: pixel-loss slice (512 groups of 4 px, 2 per thread) ----
    float inter = 0.f, uni = 0.f, contrib = 0.f;
    const int base_n = (block & 31) << 11;     // slice start within batch
#pragma unroll
    for (int q = 0; q < 2; q++) {
        int n  = base_n + ((q * T1 + tid) << 2);
        int gi = n >> 2;
        int y  = n >> 8, x = n & 255;
        int4   s4  = semv[gi];
        float4 m4  = m0v[gi];
        float4 d4  = dv[gi];
        int giu = (y > 0) ? gi - 64 : gi;      // row above (replicate at y==0)
        int4   s4u = semv[giu];
        float4 m4u = m0v[giu];
        float4 d4u = dv[giu];
        int sl0; float ml0, dl0;
        if (x > 0) { sl0 = semS[n - 1]; ml0 = m0S[n - 1]; dl0 = dS[n - 1]; }
        else       { sl0 = s4.x;        ml0 = m4.x;       dl0 = d4.x; }

        int   s[4]  = {s4.x, s4.y, s4.z, s4.w};
        int   sl[4] = {sl0, s4.x, s4.y, s4.z};
        int   su[4] = {s4u.x, s4u.y, s4u.z, s4u.w};
        float m[4]  = {m4.x, m4.y, m4.z, m4.w};
        float ml[4] = {ml0, m4.x, m4.y, m4.z};
        float mu[4] = {m4u.x, m4u.y, m4u.z, m4u.w};
        float d[4]  = {d4.x, d4.y, d4.z, d4.w};
        float dl[4] = {dl0, d4.x, d4.y, d4.z};
        float du[4] = {d4u.x, d4u.y, d4u.z, d4u.w};
#pragma unroll
        for (int e = 0; e < 4; e++) {
            float semb  = (s[e] != sl[e] || s[e] != su[e]) ? 1.f : 0.f;
            float instb = (fabsf(m[e] - ml[e]) > 0.3f ||
                           fabsf(m[e] - mu[e]) > 0.3f) ? 1.f : 0.f;
            inter += semb * instb;
            uni   += fmaxf(semb, instb);
            float gx = d[e] - dl[e], gy = d[e] - du[e];
            float ss = gx * gx + gy * gy;
            float db = sqrtf(fmaxf(ss, 1e-24f));
            float dbc = fminf(db, 2.f);
            contrib += (1.f + 3.f * dbc) * (1.f - semb) * dbc;
        }
    }
#pragma unroll
    for (int o = 16; o > 0; o >>= 1) {
        inter   += __shfl_down_sync(0xffffffffu, inter,   o);
        uni     += __shfl_down_sync(0xffffffffu, uni,     o);
        contrib += __shfl_down_sync(0xffffffffu, contrib, o);
    }
    if (lane == 0) { rI[wid] = inter; rU[wid] = uni; rD[wid] = contrib; }

    // ---- Part 2: masked histogram over the (b,m) plane ----
    const float4*  mp = (const float4*)masks + (size_t)block * (NN / 4);
    const uchar4*  sp = (const uchar4*)(g_sem8 + ((size_t)b << 16));
#pragma unroll 4
    for (int j = 0; j < 32; j++) {
        int i0 = tid + j * 512;
        float4 v0 = __ldcs(mp + i0);           // streaming: read-once data
        float4 v1 = __ldcs(mp + i0 + 256);
        uchar4 c0 = sp[i0];
        uchar4 c1 = sp[i0 + 256];
        my[(int)c0.x * T1] += v0.x;
        my[(int)c0.y * T1] += v0.y;
        my[(int)c0.z * T1] += v0.z;
        my[(int)c0.w * T1] += v0.w;
        my[(int)c1.x * T1] += v1.x;
        my[(int)c1.y * T1] += v1.y;
        my[(int)c1.z * T1] += v1.z;
        my[(int)c1.w * T1] += v1.w;
    }
    __syncwarp();

    // butterfly-reduce each thread's 27 bins across the warp
    float h[CC];
#pragma unroll
    for (int c = 0; c < CC; c++) h[c] = my[c * T1];
#pragma unroll
    for (int o = 16; o > 0; o >>= 1) {
#pragma unroll
        for (int c = 0; c < CC; c++) h[c] += __shfl_xor_sync(0xffffffffu, h[c], o);
    }
    if (lane == 0) {
#pragma unroll
        for (int c = 0; c < CC; c++) s_red[wid][c] = h[c];
    }
    __syncthreads();

    if (wid == 0) {
        float t = 0.f;
        if (lane < CC) {
#pragma unroll
            for (int w = 0; w < T1 / 32; w++) t += s_red[w][lane];
        }
        float msum = t;
#pragma unroll
        for (int o = 16; o > 0; o >>= 1) msum += __shfl_xor_sync(0xffffffffu, msum, o);
        msum += 1e-6f;
        float p = t / msum;
        p = fminf(fmaxf(p, 1e-7f), 1.0f);
        float term = (lane < CC && p > 1e-6f) ? -p * __logf(p + 1e-10f) : 0.f;
#pragma unroll
        for (int o = 16; o > 0; o >>= 1) term += __shfl_xor_sync(0xffffffffu, term, o);
        if (lane == 0) g_entArr[block] = term;
    } else if (wid == 1 && lane == 0) {
        float I = 0.f, U = 0.f, D = 0.f;
#pragma unroll
        for (int w = 0; w < T1 / 32; w++) { I += rI[w]; U += rU[w]; D += rD[w]; }
        g_blkI[block] = I;
        g_blkU[block] = U;
        g_blkD[block] = D;
    }

    // ---- Last-block finalize ----
    __threadfence();
    __syncthreads();                           // ensure wid0/wid1 stores issued
    if (tid == 0) {
        unsigned int v = atomicAdd(&g_count, 1u);
        s_isLast = (v == (unsigned int)(gridDim.x - 1));
    }
    __syncthreads();
    if (!s_isLast) return;

    // entropy: 512 entries, 2 per thread
    float e = g_entArr[tid] + g_entArr[tid + 256];
    // per-batch IoU: warp w handles batches w and w+8
    float rsum = 0.f, dsum = 0.f;
#pragma unroll
    for (int bb = wid; bb < BB; bb += 8) {
        float I = g_blkI[bb * 32 + lane];
        float U = g_blkU[bb * 32 + lane];
        float D = g_blkD[bb * 32 + lane];
#pragma unroll
        for (int o = 16; o > 0; o >>= 1) {
            I += __shfl_xor_sync(0xffffffffu, I, o);
            U += __shfl_xor_sync(0xffffffffu, U, o);
            D += __shfl_xor_sync(0xffffffffu, D, o);
        }
        rsum += I / (U + 1e-8f);
        dsum += D;
    }
#pragma unroll
    for (int o = 16; o > 0; o >>= 1) e += __shfl_xor_sync(0xffffffffu, e, o);

    __shared__ float sE[8], sR[8], sD2[8];
    if (lane == 0) { sE[wid] = e; sR[wid] = rsum; sD2[wid] = dsum; }
    __syncthreads();
    if (tid == 0) {
        float etot = 0.f, rtot = 0.f, dtot = 0.f;
#pragma unroll
        for (int w = 0; w < 8; w++) { etot += sE[w]; rtot += sR[w]; dtot += sD2[w]; }
        float lu = etot / (512.f + 1e-8f);
        float lb = 1.f - rtot * (1.f / 16.f);
        float ld = dtot * (1.f / ((float)BB * (float)NN));
        out[0] = lu;
        out[1] = lb;
        out[2] = ld;
        out[3] = 0.3f * lu + 0.2f * lb + 0.2f * ld;
        g_count = 0;                           // reset for next graph replay
    }
}

// ---------------------------------------------------------------------------
extern "C" void kernel_launch(void* const* d_in, const int* in_sizes, int n_in,
                              void* d_out, int out_size) {
    const int*   sem   = (const int*)d_in[0];
    const float* masks = (const float*)d_in[1];
    const float* depth = (const float*)d_in[2];
    float* out = (float*)d_out;

    pack_kernel<<<(BB * NN / 4) / 256, 256>>>(sem);              // 1024 blocks
    fused_kernel<<<BB * MM, T1>>>(sem, masks, depth, out);       // 512 blocks
}